// round 2
// baseline (speedup 1.0000x reference)
#include <cuda_runtime.h>
#include <math.h>

#define NNODES 100000
#define NEDGES 1600000
#define NGRAPH 4096
#define INFEAT 74
#define HID    128
#define NCONV  3
#define NGRAM  6
#define BN_EPS 1e-5f

// ---------------- scratch (static device allocations only) ----------------
__device__ __align__(256) float g_hA[(size_t)NNODES * HID];        // 51.2 MB
__device__ __align__(256) float g_hB[(size_t)NNODES * HID];        // 51.2 MB
__device__ int   g_row_off[NNODES + 1];
__device__ int   g_cursor[NNODES];
__device__ int   g_csr[NEDGES];
__device__ __align__(16) float g_sum[HID];
__device__ __align__(16) float g_sumsq[HID];
__device__ __align__(16) float g_scale[HID];
__device__ __align__(16) float g_shift[HID];
__device__ __align__(16) float g_combined[NGRAPH * HID];
__device__ int   g_gstart[NGRAPH + 1];
__device__ float g_wsm[NGRAM];

// ---------------- small setup kernels ----------------
__global__ void zero_misc_kernel() {
    int i = blockIdx.x * blockDim.x + threadIdx.x;
    int n = NGRAPH * HID;
    if (i < n) g_combined[i] = 0.f;
    if (i < NNODES) g_cursor[i] = 0;
    if (i < HID) { g_sum[i] = 0.f; g_sumsq[i] = 0.f; }
}

__global__ void softmax_kernel(const float* __restrict__ w) {
    // single thread; NGRAM = 6
    float m = w[0];
    for (int i = 1; i < NGRAM; i++) m = fmaxf(m, w[i]);
    float s = 0.f;
    float e[NGRAM];
    for (int i = 0; i < NGRAM; i++) { e[i] = expf(w[i] - m); s += e[i]; }
    for (int i = 0; i < NGRAM; i++) g_wsm[i] = e[i] / s;
}

__global__ void hist_kernel(const int* __restrict__ dst) {
    int i = blockIdx.x * blockDim.x + threadIdx.x;
    if (i < NEDGES) atomicAdd(&g_cursor[dst[i]], 1);
}

__global__ void scan_kernel() {
    // single block, 1024 threads; exclusive scan of counts (in g_cursor)
    // writes g_row_off[0..N] and resets g_cursor to row starts
    __shared__ int s_part[1024];
    const int T = 1024;
    int t = threadIdx.x;
    const int chunk = (NNODES + T - 1) / T;
    int begin = t * chunk;
    int end = begin + chunk; if (end > NNODES) end = NNODES;
    int sum = 0;
    for (int i = begin; i < end; i++) sum += g_cursor[i];
    s_part[t] = sum;
    __syncthreads();
    // Hillis-Steele inclusive scan
    for (int off = 1; off < T; off <<= 1) {
        int v = (t >= off) ? s_part[t - off] : 0;
        __syncthreads();
        s_part[t] += v;
        __syncthreads();
    }
    int run = (t == 0) ? 0 : s_part[t - 1];
    for (int i = begin; i < end; i++) {
        int c = g_cursor[i];
        g_row_off[i] = run;
        g_cursor[i] = run;
        run += c;
    }
    if (t == T - 1) g_row_off[NNODES] = s_part[T - 1];
}

__global__ void scatter_kernel(const int* __restrict__ src, const int* __restrict__ dst) {
    int i = blockIdx.x * blockDim.x + threadIdx.x;
    if (i < NEDGES) {
        int pos = atomicAdd(&g_cursor[dst[i]], 1);
        g_csr[pos] = src[i];
    }
}

__global__ void gstart_kernel(const int* __restrict__ gids) {
    int i = blockIdx.x * blockDim.x + threadIdx.x;
    if (i >= NNODES) return;
    int g = gids[i];
    int p = (i == 0) ? -1 : gids[i - 1];
    for (int q = p + 1; q <= g; q++) g_gstart[q] = i;
    if (i == NNODES - 1) {
        for (int q = g + 1; q <= NGRAPH; q++) g_gstart[q] = NNODES;
    }
}

// ---------------- input projection GEMM: h0 = features @ W_in ----------------
// BM=64 rows per block, 256 threads, full K=74 and W in smem.
constexpr int IN_SMEM_BYTES = (64 * 75 + INFEAT * HID) * 4;

__global__ __launch_bounds__(256, 2)
void ingemm_kernel(const float* __restrict__ feat, const float* __restrict__ Win,
                   float* __restrict__ hout) {
    extern __shared__ float sm[];
    float* sm_f = sm;                 // [64][75]
    float* sm_w = sm + 64 * 75;       // [74][128]
    int tid = threadIdx.x;
    int row0 = blockIdx.x * 64;

    for (int idx = tid; idx < 64 * INFEAT; idx += 256) {
        int r = idx / INFEAT, k = idx % INFEAT;
        int rr = row0 + r;
        sm_f[r * 75 + k] = (rr < NNODES) ? feat[(size_t)rr * INFEAT + k] : 0.f;
    }
    for (int idx = tid * 4; idx < INFEAT * HID; idx += 256 * 4) {
        *(float4*)&sm_w[idx] = *(const float4*)&Win[idx];
    }
    __syncthreads();

    int rg = tid >> 4;   // 0..15 -> 4 rows each
    int cg = tid & 15;   // 0..15 -> 8 cols each
    float acc[4][8];
    #pragma unroll
    for (int i = 0; i < 4; i++)
        #pragma unroll
        for (int j = 0; j < 8; j++) acc[i][j] = 0.f;

    const float* m0 = sm_f + (rg * 4 + 0) * 75;
    const float* m1 = m0 + 75;
    const float* m2 = m1 + 75;
    const float* m3 = m2 + 75;
    const float* wp = sm_w + cg * 8;
    #pragma unroll 2
    for (int k = 0; k < INFEAT; k++) {
        float4 b0 = *(const float4*)(wp + k * HID);
        float4 b1 = *(const float4*)(wp + k * HID + 4);
        float a[4] = {m0[k], m1[k], m2[k], m3[k]};
        #pragma unroll
        for (int i = 0; i < 4; i++) {
            acc[i][0] = fmaf(a[i], b0.x, acc[i][0]);
            acc[i][1] = fmaf(a[i], b0.y, acc[i][1]);
            acc[i][2] = fmaf(a[i], b0.z, acc[i][2]);
            acc[i][3] = fmaf(a[i], b0.w, acc[i][3]);
            acc[i][4] = fmaf(a[i], b1.x, acc[i][4]);
            acc[i][5] = fmaf(a[i], b1.y, acc[i][5]);
            acc[i][6] = fmaf(a[i], b1.z, acc[i][6]);
            acc[i][7] = fmaf(a[i], b1.w, acc[i][7]);
        }
    }
    #pragma unroll
    for (int i = 0; i < 4; i++) {
        int r = row0 + rg * 4 + i;
        if (r < NNODES) {
            float4 o0 = make_float4(acc[i][0], acc[i][1], acc[i][2], acc[i][3]);
            float4 o1 = make_float4(acc[i][4], acc[i][5], acc[i][6], acc[i][7]);
            *(float4*)&hout[(size_t)r * HID + cg * 8]     = o0;
            *(float4*)&hout[(size_t)r * HID + cg * 8 + 4] = o1;
        }
    }
}

// ---------------- fused conv step: aggregate + GEMM + BN stats ----------------
// Block: 64 dst rows, 256 threads. smem: m-tile [64][129] + W [128][128].
constexpr int CONV_SMEM_BYTES = (64 * 129 + HID * HID) * 4;

template <bool APPLY_BN>
__global__ __launch_bounds__(256, 2)
void conv_kernel(const float* __restrict__ hin, float* __restrict__ hout,
                 const float* __restrict__ W) {
    extern __shared__ float sm[];
    float* sm_m = sm;                 // [64][129] padded (odd stride -> scalar stores!)
    float* sm_w = sm + 64 * 129;      // [128][128]
    int tid = threadIdx.x;
    int warp = tid >> 5, lane = tid & 31;
    int row0 = blockIdx.x * 64;

    // stage W
    for (int idx = tid * 4; idx < HID * HID; idx += 256 * 4) {
        *(float4*)&sm_w[idx] = *(const float4*)&W[idx];
    }

    float4 sc, sh;
    if (APPLY_BN) {
        sc = *(const float4*)&g_scale[lane * 4];
        sh = *(const float4*)&g_shift[lane * 4];
    }

    // phase 1: aggregate m rows (each warp does 8 rows, lane covers 4 features)
    for (int rr = warp; rr < 64; rr += 8) {
        int r = row0 + rr;
        float4 acc = make_float4(0.f, 0.f, 0.f, 0.f);
        if (r < NNODES) {
            int s = g_row_off[r], e = g_row_off[r + 1];
            #pragma unroll 4
            for (int i = s; i < e; i++) {
                int u = g_csr[i];
                float4 v = *(const float4*)&hin[(size_t)u * HID + lane * 4];
                if (APPLY_BN) {
                    v.x = fmaxf(fmaf(v.x, sc.x, sh.x), 0.f);
                    v.y = fmaxf(fmaf(v.y, sc.y, sh.y), 0.f);
                    v.z = fmaxf(fmaf(v.z, sc.z, sh.z), 0.f);
                    v.w = fmaxf(fmaf(v.w, sc.w, sh.w), 0.f);
                }
                acc.x += v.x; acc.y += v.y; acc.z += v.z; acc.w += v.w;
            }
        }
        // scalar stores: row stride 129 floats is NOT 16B-aligned, STS.128 would trap
        float* mp = sm_m + rr * 129 + lane * 4;
        mp[0] = acc.x; mp[1] = acc.y; mp[2] = acc.z; mp[3] = acc.w;
    }
    __syncthreads();

    // phase 2: y-tile = m-tile @ W
    int rg = tid >> 4;
    int cg = tid & 15;
    float acc[4][8];
    #pragma unroll
    for (int i = 0; i < 4; i++)
        #pragma unroll
        for (int j = 0; j < 8; j++) acc[i][j] = 0.f;

    const float* m0 = sm_m + (rg * 4 + 0) * 129;
    const float* m1 = m0 + 129;
    const float* m2 = m1 + 129;
    const float* m3 = m2 + 129;
    const float* wp = sm_w + cg * 8;
    #pragma unroll 4
    for (int k = 0; k < HID; k++) {
        float4 b0 = *(const float4*)(wp + k * HID);
        float4 b1 = *(const float4*)(wp + k * HID + 4);
        float a[4] = {m0[k], m1[k], m2[k], m3[k]};
        #pragma unroll
        for (int i = 0; i < 4; i++) {
            acc[i][0] = fmaf(a[i], b0.x, acc[i][0]);
            acc[i][1] = fmaf(a[i], b0.y, acc[i][1]);
            acc[i][2] = fmaf(a[i], b0.z, acc[i][2]);
            acc[i][3] = fmaf(a[i], b0.w, acc[i][3]);
            acc[i][4] = fmaf(a[i], b1.x, acc[i][4]);
            acc[i][5] = fmaf(a[i], b1.y, acc[i][5]);
            acc[i][6] = fmaf(a[i], b1.z, acc[i][6]);
            acc[i][7] = fmaf(a[i], b1.w, acc[i][7]);
        }
    }

    // epilogue: write y, accumulate per-column sum / sumsq
    float csum[8], csq[8];
    #pragma unroll
    for (int j = 0; j < 8; j++) { csum[j] = 0.f; csq[j] = 0.f; }
    #pragma unroll
    for (int i = 0; i < 4; i++) {
        int r = row0 + rg * 4 + i;
        if (r < NNODES) {
            float4 o0 = make_float4(acc[i][0], acc[i][1], acc[i][2], acc[i][3]);
            float4 o1 = make_float4(acc[i][4], acc[i][5], acc[i][6], acc[i][7]);
            *(float4*)&hout[(size_t)r * HID + cg * 8]     = o0;
            *(float4*)&hout[(size_t)r * HID + cg * 8 + 4] = o1;
            #pragma unroll
            for (int j = 0; j < 8; j++) {
                csum[j] += acc[i][j];
                csq[j]  += acc[i][j] * acc[i][j];
            }
        }
    }
    __syncthreads();      // done reading sm_m/sm_w; reuse sm_m for stats
    float* s_sum = sm_m;
    float* s_sq  = sm_m + HID;
    if (tid < HID) { s_sum[tid] = 0.f; s_sq[tid] = 0.f; }
    __syncthreads();
    #pragma unroll
    for (int j = 0; j < 8; j++) {
        atomicAdd(&s_sum[cg * 8 + j], csum[j]);
        atomicAdd(&s_sq[cg * 8 + j],  csq[j]);
    }
    __syncthreads();
    if (tid < HID) {
        atomicAdd(&g_sum[tid],   s_sum[tid]);
        atomicAdd(&g_sumsq[tid], s_sq[tid]);
    }
}

// ---------------- BN parameters for the step just computed ----------------
__global__ void bnparam_kernel(const float* __restrict__ gamma,
                               const float* __restrict__ beta) {
    int c = threadIdx.x;
    float s = g_sum[c], sq = g_sumsq[c];
    const float invN = 1.f / (float)NNODES;
    float mean = s * invN;
    float var = sq * invN - mean * mean;
    float inv = rsqrtf(var + BN_EPS);
    float scl = gamma[c] * inv;
    g_scale[c] = scl;
    g_shift[c] = beta[c] - mean * scl;
    g_sum[c] = 0.f;
    g_sumsq[c] = 0.f;
}

// ---------------- per-graph pooling with lazy BN+ReLU ----------------
__global__ void pool_kernel(const float* __restrict__ h, int n) {
    int g = blockIdx.x;
    int c = threadIdx.x;
    int s = g_gstart[g], e = g_gstart[g + 1];
    float sc = g_scale[c], sh = g_shift[c];
    float acc = 0.f;
    for (int i = s; i < e; i++)
        acc += fmaxf(fmaf(h[(size_t)i * HID + c], sc, sh), 0.f);
    g_combined[g * HID + c] += g_wsm[n] * acc;
}

// ---------------- head MLP ----------------
__global__ void final_kernel(const float* __restrict__ W1, const float* __restrict__ b1,
                             const float* __restrict__ W2, const float* __restrict__ b2,
                             float* __restrict__ out) {
    __shared__ float srow[HID];
    __shared__ float red[HID];
    int g = blockIdx.x, t = threadIdx.x;
    srow[t] = g_combined[g * HID + t];
    __syncthreads();
    float acc = b1[t];
    #pragma unroll 8
    for (int k = 0; k < HID; k++)
        acc = fmaf(srow[k], W1[k * HID + t], acc);
    float v = (acc > 0.f) ? acc : 0.01f * acc;
    red[t] = v * W2[t];
    __syncthreads();
    for (int off = 64; off > 0; off >>= 1) {
        if (t < off) red[t] += red[t + off];
        __syncthreads();
    }
    if (t == 0) out[g] = 1.f / (1.f + expf(-(red[0] + b2[0])));
}

// ---------------- host launch ----------------
extern "C" void kernel_launch(void* const* d_in, const int* in_sizes, int n_in,
                              void* d_out, int out_size) {
    const float* features = (const float*)d_in[0];
    const float* W_in     = (const float*)d_in[1];
    const float* conv_w   = (const float*)d_in[2];
    const float* bn_gamma = (const float*)d_in[3];
    const float* bn_beta  = (const float*)d_in[4];
    const float* ngram_w  = (const float*)d_in[5];
    const float* W1       = (const float*)d_in[6];
    const float* b1       = (const float*)d_in[7];
    const float* W2       = (const float*)d_in[8];
    const float* b2       = (const float*)d_in[9];
    const int*   src      = (const int*)d_in[10];
    const int*   dst      = (const int*)d_in[11];
    const int*   gids     = (const int*)d_in[12];
    float* out = (float*)d_out;

    cudaFuncSetAttribute(conv_kernel<true>,  cudaFuncAttributeMaxDynamicSharedMemorySize, CONV_SMEM_BYTES);
    cudaFuncSetAttribute(conv_kernel<false>, cudaFuncAttributeMaxDynamicSharedMemorySize, CONV_SMEM_BYTES);
    cudaFuncSetAttribute(ingemm_kernel,      cudaFuncAttributeMaxDynamicSharedMemorySize, IN_SMEM_BYTES);

    float *hA, *hB;
    cudaGetSymbolAddress((void**)&hA, g_hA);
    cudaGetSymbolAddress((void**)&hB, g_hB);

    // setup
    zero_misc_kernel<<<(NGRAPH * HID + 255) / 256, 256>>>();
    softmax_kernel<<<1, 1>>>(ngram_w);
    hist_kernel<<<(NEDGES + 255) / 256, 256>>>(dst);
    scan_kernel<<<1, 1024>>>();
    scatter_kernel<<<(NEDGES + 255) / 256, 256>>>(src, dst);
    gstart_kernel<<<(NNODES + 255) / 256, 256>>>(gids);

    const int NBLK = (NNODES + 63) / 64;   // 1563
    ingemm_kernel<<<NBLK, 256, IN_SMEM_BYTES>>>(features, W_in, hA);

    float* cur = hA;
    float* nxt = hB;
    bool first = true;
    for (int n = 0; n < NGRAM; n++) {
        for (int j = 0; j < NCONV; j++) {
            const float* Wj = conv_w + (size_t)j * HID * HID;
            if (first) {
                conv_kernel<false><<<NBLK, 256, CONV_SMEM_BYTES>>>(cur, nxt, Wj);
                first = false;
            } else {
                conv_kernel<true><<<NBLK, 256, CONV_SMEM_BYTES>>>(cur, nxt, Wj);
            }
            bnparam_kernel<<<1, HID>>>(bn_gamma + j * HID, bn_beta + j * HID);
            float* t = cur; cur = nxt; nxt = t;
        }
        pool_kernel<<<NGRAPH, HID>>>(cur, n);
    }
    final_kernel<<<NGRAPH, HID>>>(W1, b1, W2, b2, out);
}

// round 5
// speedup vs baseline: 1.0348x; 1.0348x over previous
#include <cuda_runtime.h>
#include <math.h>

#define NNODES 100000
#define NEDGES 1600000
#define NGRAPH 4096
#define INFEAT 74
#define HID    128
#define NCONV  3
#define NGRAM  6
#define BN_EPS 1e-5f

#define NSB 98            // scan blocks: ceil(100000/1024)

typedef unsigned long long u64;

// ---------------- scratch (static device allocations only) ----------------
__device__ __align__(256) float g_hA[(size_t)NNODES * HID];
__device__ __align__(256) float g_hB[(size_t)NNODES * HID];
__device__ int   g_row_off[NNODES + 1];
__device__ int   g_cursor[NNODES];
__device__ int   g_csr[NEDGES];
__device__ __align__(16) float g_sum[HID];
__device__ __align__(16) float g_sumsq[HID];
__device__ __align__(16) float g_scale[HID];
__device__ __align__(16) float g_shift[HID];
__device__ __align__(16) float g_combined[NGRAPH * HID];
__device__ int   g_gstart[NGRAPH + 1];
__device__ float g_wsm[NGRAM];
__device__ int   g_blocksum[NSB];
__device__ int   g_blockbase[NSB];

// ---------------- f32x2 helpers (GEMM only; fma.rn.f32x2 is valid PTX) -------
__device__ __forceinline__ u64 pack2(float a) {
    u64 r; asm("mov.b64 %0, {%1, %1};" : "=l"(r) : "f"(a)); return r;
}
__device__ __forceinline__ void unpack2(u64 v, float& lo, float& hi) {
    asm("mov.b64 {%0, %1}, %2;" : "=f"(lo), "=f"(hi) : "l"(v));
}
__device__ __forceinline__ void fma2(u64& d, u64 a, u64 b) {
    asm("fma.rn.f32x2 %0, %1, %2, %0;" : "+l"(d) : "l"(a), "l"(b));
}

// ---------------- setup: zeroing + gstart + softmax (one kernel) ----------------
__global__ void setup_kernel(const int* __restrict__ gids, const float* __restrict__ w) {
    int i = blockIdx.x * blockDim.x + threadIdx.x;
    if (i < NGRAPH * HID) g_combined[i] = 0.f;
    if (i < NNODES) g_cursor[i] = 0;
    if (i < HID) { g_sum[i] = 0.f; g_sumsq[i] = 0.f; }
    if (i < NNODES) {
        int g = gids[i];
        int p = (i == 0) ? -1 : gids[i - 1];
        for (int q = p + 1; q <= g; q++) g_gstart[q] = i;
        if (i == NNODES - 1)
            for (int q = g + 1; q <= NGRAPH; q++) g_gstart[q] = NNODES;
    }
    if (i == 0) {
        float m = w[0];
        for (int k = 1; k < NGRAM; k++) m = fmaxf(m, w[k]);
        float s = 0.f, e[NGRAM];
        for (int k = 0; k < NGRAM; k++) { e[k] = expf(w[k] - m); s += e[k]; }
        for (int k = 0; k < NGRAM; k++) g_wsm[k] = e[k] / s;
    }
}

__global__ void hist_kernel(const int* __restrict__ dst) {
    int i = blockIdx.x * blockDim.x + threadIdx.x;
    if (i < NEDGES) atomicAdd(&g_cursor[dst[i]], 1);
}

// ---------------- spin-free 3-phase scan ----------------
__global__ void scanA_kernel() {
    __shared__ int s_red[32];
    int t = threadIdx.x, b = blockIdx.x;
    int i = b * 1024 + t;
    int v = (i < NNODES) ? g_cursor[i] : 0;
    for (int off = 16; off > 0; off >>= 1) v += __shfl_down_sync(0xffffffff, v, off);
    if ((t & 31) == 0) s_red[t >> 5] = v;
    __syncthreads();
    if (t < 32) {
        int w = s_red[t];
        for (int off = 16; off > 0; off >>= 1) w += __shfl_down_sync(0xffffffff, w, off);
        if (t == 0) g_blocksum[b] = w;
    }
}

__global__ void scanB_kernel() {
    __shared__ int s_v[128];
    int t = threadIdx.x;
    int v = (t < NSB) ? g_blocksum[t] : 0;
    s_v[t] = v;
    __syncthreads();
    #pragma unroll
    for (int off = 1; off < 128; off <<= 1) {
        int u = (t >= off) ? s_v[t - off] : 0;
        __syncthreads();
        s_v[t] += u;
        __syncthreads();
    }
    if (t < NSB) g_blockbase[t] = s_v[t] - v;
    if (t == NSB - 1) g_row_off[NNODES] = s_v[t];
}

__global__ void scanC_kernel() {
    __shared__ int s_sc[1024];
    int t = threadIdx.x, b = blockIdx.x;
    int i = b * 1024 + t;
    int cnt = (i < NNODES) ? g_cursor[i] : 0;
    s_sc[t] = cnt;
    __syncthreads();
    #pragma unroll
    for (int off = 1; off < 1024; off <<= 1) {
        int v = (t >= off) ? s_sc[t - off] : 0;
        __syncthreads();
        s_sc[t] += v;
        __syncthreads();
    }
    int excl = g_blockbase[b] + s_sc[t] - cnt;
    if (i < NNODES) { g_row_off[i] = excl; g_cursor[i] = excl; }
}

__global__ void scatter_kernel(const int* __restrict__ src, const int* __restrict__ dst) {
    int i = blockIdx.x * blockDim.x + threadIdx.x;
    if (i < NEDGES) {
        int pos = atomicAdd(&g_cursor[dst[i]], 1);
        g_csr[pos] = src[i];
    }
}

// ---------------- input projection GEMM: h0 = features @ W_in ----------------
constexpr int IN_SMEM_BYTES = (64 * 75 + INFEAT * HID) * 4;

__global__ __launch_bounds__(256, 2)
void ingemm_kernel(const float* __restrict__ feat, const float* __restrict__ Win,
                   float* __restrict__ hout) {
    extern __shared__ float sm[];
    float* sm_f = sm;                 // [64][75]
    float* sm_w = sm + 64 * 75;       // [74][128]
    int tid = threadIdx.x;
    int row0 = blockIdx.x * 64;

    for (int idx = tid; idx < 64 * INFEAT; idx += 256) {
        int r = idx / INFEAT, k = idx % INFEAT;
        int rr = row0 + r;
        sm_f[r * 75 + k] = (rr < NNODES) ? feat[(size_t)rr * INFEAT + k] : 0.f;
    }
    for (int idx = tid * 4; idx < INFEAT * HID; idx += 256 * 4) {
        *(float4*)&sm_w[idx] = *(const float4*)&Win[idx];
    }
    __syncthreads();

    int rg = tid >> 4;
    int cg = tid & 15;
    u64 acc2[4][4];
    #pragma unroll
    for (int i = 0; i < 4; i++)
        #pragma unroll
        for (int j = 0; j < 4; j++) acc2[i][j] = 0ull;

    const float* m0 = sm_f + (rg * 4 + 0) * 75;
    const float* m1 = m0 + 75;
    const float* m2 = m1 + 75;
    const float* m3 = m2 + 75;
    const float* wp = sm_w + cg * 8;
    #pragma unroll 2
    for (int k = 0; k < INFEAT; k++) {
        ulonglong2 q0 = *(const ulonglong2*)(wp + k * HID);
        ulonglong2 q1 = *(const ulonglong2*)(wp + k * HID + 4);
        u64 a0 = pack2(m0[k]), a1 = pack2(m1[k]), a2 = pack2(m2[k]), a3 = pack2(m3[k]);
        fma2(acc2[0][0], a0, q0.x); fma2(acc2[0][1], a0, q0.y);
        fma2(acc2[0][2], a0, q1.x); fma2(acc2[0][3], a0, q1.y);
        fma2(acc2[1][0], a1, q0.x); fma2(acc2[1][1], a1, q0.y);
        fma2(acc2[1][2], a1, q1.x); fma2(acc2[1][3], a1, q1.y);
        fma2(acc2[2][0], a2, q0.x); fma2(acc2[2][1], a2, q0.y);
        fma2(acc2[2][2], a2, q1.x); fma2(acc2[2][3], a2, q1.y);
        fma2(acc2[3][0], a3, q0.x); fma2(acc2[3][1], a3, q0.y);
        fma2(acc2[3][2], a3, q1.x); fma2(acc2[3][3], a3, q1.y);
    }
    #pragma unroll
    for (int i = 0; i < 4; i++) {
        int r = row0 + rg * 4 + i;
        if (r < NNODES) {
            float o[8];
            #pragma unroll
            for (int j = 0; j < 4; j++) unpack2(acc2[i][j], o[2 * j], o[2 * j + 1]);
            *(float4*)&hout[(size_t)r * HID + cg * 8]     = *(float4*)&o[0];
            *(float4*)&hout[(size_t)r * HID + cg * 8 + 4] = *(float4*)&o[4];
        }
    }
}

// ---------------- fused conv step: aggregate + GEMM + BN stats ----------------
constexpr int CONV_SMEM_BYTES = (64 * 129 + HID * HID) * 4;

template <bool APPLY_BN>
__global__ __launch_bounds__(256, 2)
void conv_kernel(const float* __restrict__ hin, float* __restrict__ hout,
                 const float* __restrict__ W) {
    extern __shared__ float sm[];
    float* sm_m = sm;                 // [64][129] (odd stride -> scalar stores)
    float* sm_w = sm + 64 * 129;      // [128][128]
    int tid = threadIdx.x;
    int warp = tid >> 5, lane = tid & 31;
    int row0 = blockIdx.x * 64;

    for (int idx = tid * 4; idx < HID * HID; idx += 256 * 4) {
        *(float4*)&sm_w[idx] = *(const float4*)&W[idx];
    }

    float4 sc, sh;
    if (APPLY_BN) {
        sc = *(const float4*)&g_scale[lane * 4];
        sh = *(const float4*)&g_shift[lane * 4];
    }

    // phase 1: aggregate m rows (L2-BW bound; plain scalar math, float4 loads)
    for (int rr = warp; rr < 64; rr += 8) {
        int r = row0 + rr;
        float4 acc = make_float4(0.f, 0.f, 0.f, 0.f);
        if (r < NNODES) {
            int s = g_row_off[r], e = g_row_off[r + 1];
            #pragma unroll 4
            for (int i = s; i < e; i++) {
                int u = g_csr[i];
                float4 v = *(const float4*)&hin[(size_t)u * HID + lane * 4];
                if (APPLY_BN) {
                    v.x = fmaxf(fmaf(v.x, sc.x, sh.x), 0.f);
                    v.y = fmaxf(fmaf(v.y, sc.y, sh.y), 0.f);
                    v.z = fmaxf(fmaf(v.z, sc.z, sh.z), 0.f);
                    v.w = fmaxf(fmaf(v.w, sc.w, sh.w), 0.f);
                }
                acc.x += v.x; acc.y += v.y; acc.z += v.z; acc.w += v.w;
            }
        }
        float* mp = sm_m + rr * 129 + lane * 4;
        mp[0] = acc.x; mp[1] = acc.y; mp[2] = acc.z; mp[3] = acc.w;
    }
    __syncthreads();

    // phase 2: y-tile = m-tile @ W, packed f32x2 FMA (issue-bound -> 2x)
    int rg = tid >> 4;
    int cg = tid & 15;
    u64 acc2[4][4];
    #pragma unroll
    for (int i = 0; i < 4; i++)
        #pragma unroll
        for (int j = 0; j < 4; j++) acc2[i][j] = 0ull;

    const float* m0 = sm_m + (rg * 4 + 0) * 129;
    const float* m1 = m0 + 129;
    const float* m2 = m1 + 129;
    const float* m3 = m2 + 129;
    const float* wp = sm_w + cg * 8;
    #pragma unroll 4
    for (int k = 0; k < HID; k++) {
        ulonglong2 q0 = *(const ulonglong2*)(wp + k * HID);
        ulonglong2 q1 = *(const ulonglong2*)(wp + k * HID + 4);
        u64 a0 = pack2(m0[k]), a1 = pack2(m1[k]), a2 = pack2(m2[k]), a3 = pack2(m3[k]);
        fma2(acc2[0][0], a0, q0.x); fma2(acc2[0][1], a0, q0.y);
        fma2(acc2[0][2], a0, q1.x); fma2(acc2[0][3], a0, q1.y);
        fma2(acc2[1][0], a1, q0.x); fma2(acc2[1][1], a1, q0.y);
        fma2(acc2[1][2], a1, q1.x); fma2(acc2[1][3], a1, q1.y);
        fma2(acc2[2][0], a2, q0.x); fma2(acc2[2][1], a2, q0.y);
        fma2(acc2[2][2], a2, q1.x); fma2(acc2[2][3], a2, q1.y);
        fma2(acc2[3][0], a3, q0.x); fma2(acc2[3][1], a3, q0.y);
        fma2(acc2[3][2], a3, q1.x); fma2(acc2[3][3], a3, q1.y);
    }

    // epilogue: write y, accumulate per-column sum / sumsq
    float csum[8], csq[8];
    #pragma unroll
    for (int j = 0; j < 8; j++) { csum[j] = 0.f; csq[j] = 0.f; }
    #pragma unroll
    for (int i = 0; i < 4; i++) {
        int r = row0 + rg * 4 + i;
        if (r < NNODES) {
            float o[8];
            #pragma unroll
            for (int j = 0; j < 4; j++) unpack2(acc2[i][j], o[2 * j], o[2 * j + 1]);
            *(float4*)&hout[(size_t)r * HID + cg * 8]     = *(float4*)&o[0];
            *(float4*)&hout[(size_t)r * HID + cg * 8 + 4] = *(float4*)&o[4];
            #pragma unroll
            for (int j = 0; j < 8; j++) {
                csum[j] += o[j];
                csq[j]  += o[j] * o[j];
            }
        }
    }
    __syncthreads();      // done with sm_m/sm_w; reuse sm_m for stats
    float* s_sum = sm_m;
    float* s_sq  = sm_m + HID;
    if (tid < HID) { s_sum[tid] = 0.f; s_sq[tid] = 0.f; }
    __syncthreads();
    #pragma unroll
    for (int j = 0; j < 8; j++) {
        atomicAdd(&s_sum[cg * 8 + j], csum[j]);
        atomicAdd(&s_sq[cg * 8 + j],  csq[j]);
    }
    __syncthreads();
    if (tid < HID) {
        atomicAdd(&g_sum[tid],   s_sum[tid]);
        atomicAdd(&g_sumsq[tid], s_sq[tid]);
    }
}

// ---------------- BN parameters for the step just computed ----------------
__global__ void bnparam_kernel(const float* __restrict__ gamma,
                               const float* __restrict__ beta) {
    int c = threadIdx.x;
    float s = g_sum[c], sq = g_sumsq[c];
    const float invN = 1.f / (float)NNODES;
    float mean = s * invN;
    float var = sq * invN - mean * mean;
    float inv = rsqrtf(var + BN_EPS);
    float scl = gamma[c] * inv;
    g_scale[c] = scl;
    g_shift[c] = beta[c] - mean * scl;
    g_sum[c] = 0.f;
    g_sumsq[c] = 0.f;
}

// ---------------- per-graph pooling with lazy BN+ReLU ----------------
__global__ void pool_kernel(const float* __restrict__ h, int n) {
    int g = blockIdx.x;
    int c = threadIdx.x;
    int s = g_gstart[g], e = g_gstart[g + 1];
    float sc = g_scale[c], sh = g_shift[c];
    float acc = 0.f;
    for (int i = s; i < e; i++)
        acc += fmaxf(fmaf(h[(size_t)i * HID + c], sc, sh), 0.f);
    g_combined[g * HID + c] += g_wsm[n] * acc;
}

// ---------------- head MLP ----------------
__global__ void final_kernel(const float* __restrict__ W1, const float* __restrict__ b1,
                             const float* __restrict__ W2, const float* __restrict__ b2,
                             float* __restrict__ out) {
    __shared__ float srow[HID];
    __shared__ float red[HID];
    int g = blockIdx.x, t = threadIdx.x;
    srow[t] = g_combined[g * HID + t];
    __syncthreads();
    float acc = b1[t];
    #pragma unroll 8
    for (int k = 0; k < HID; k++)
        acc = fmaf(srow[k], W1[k * HID + t], acc);
    float v = (acc > 0.f) ? acc : 0.01f * acc;
    red[t] = v * W2[t];
    __syncthreads();
    for (int off = 64; off > 0; off >>= 1) {
        if (t < off) red[t] += red[t + off];
        __syncthreads();
    }
    if (t == 0) out[g] = 1.f / (1.f + expf(-(red[0] + b2[0])));
}

// ---------------- host launch ----------------
extern "C" void kernel_launch(void* const* d_in, const int* in_sizes, int n_in,
                              void* d_out, int out_size) {
    const float* features = (const float*)d_in[0];
    const float* W_in     = (const float*)d_in[1];
    const float* conv_w   = (const float*)d_in[2];
    const float* bn_gamma = (const float*)d_in[3];
    const float* bn_beta  = (const float*)d_in[4];
    const float* ngram_w  = (const float*)d_in[5];
    const float* W1       = (const float*)d_in[6];
    const float* b1       = (const float*)d_in[7];
    const float* W2       = (const float*)d_in[8];
    const float* b2       = (const float*)d_in[9];
    const int*   src      = (const int*)d_in[10];
    const int*   dst      = (const int*)d_in[11];
    const int*   gids     = (const int*)d_in[12];
    float* out = (float*)d_out;

    cudaFuncSetAttribute(conv_kernel<true>,  cudaFuncAttributeMaxDynamicSharedMemorySize, CONV_SMEM_BYTES);
    cudaFuncSetAttribute(conv_kernel<false>, cudaFuncAttributeMaxDynamicSharedMemorySize, CONV_SMEM_BYTES);
    cudaFuncSetAttribute(ingemm_kernel,      cudaFuncAttributeMaxDynamicSharedMemorySize, IN_SMEM_BYTES);

    float *hA, *hB;
    cudaGetSymbolAddress((void**)&hA, g_hA);
    cudaGetSymbolAddress((void**)&hB, g_hB);

    setup_kernel<<<(NGRAPH * HID + 255) / 256, 256>>>(gids, ngram_w);
    hist_kernel<<<(NEDGES + 255) / 256, 256>>>(dst);
    scanA_kernel<<<NSB, 1024>>>();
    scanB_kernel<<<1, 128>>>();
    scanC_kernel<<<NSB, 1024>>>();
    scatter_kernel<<<(NEDGES + 255) / 256, 256>>>(src, dst);

    const int NBLK = (NNODES + 63) / 64;   // 1563
    ingemm_kernel<<<NBLK, 256, IN_SMEM_BYTES>>>(features, W_in, hA);

    float* cur = hA;
    float* nxt = hB;
    bool first = true;
    for (int n = 0; n < NGRAM; n++) {
        for (int j = 0; j < NCONV; j++) {
            const float* Wj = conv_w + (size_t)j * HID * HID;
            if (first) {
                conv_kernel<false><<<NBLK, 256, CONV_SMEM_BYTES>>>(cur, nxt, Wj);
                first = false;
            } else {
                conv_kernel<true><<<NBLK, 256, CONV_SMEM_BYTES>>>(cur, nxt, Wj);
            }
            bnparam_kernel<<<1, HID>>>(bn_gamma + j * HID, bn_beta + j * HID);
            float* t = cur; cur = nxt; nxt = t;
        }
        pool_kernel<<<NGRAPH, HID>>>(cur, n);
    }
    final_kernel<<<NGRAPH, HID>>>(W1, b1, W2, b2, out);
}